// round 1
// baseline (speedup 1.0000x reference)
#include <cuda_runtime.h>
#include <cstdint>
#include <cstddef>

#define HN     16
#define DMODEL 1024
#define NSEQ   2048
#define NB     2
#define HD     64
#define LN_EPS 1e-5f

// ---------------- scratch (device globals; no allocation allowed) ----------
__device__ float g_q [(size_t)NB * NSEQ * DMODEL];        // 16.8 MB
__device__ float g_kv[(size_t)NB * NSEQ * 2048];          // 33.5 MB (k | v)
__device__ float g_E [(size_t)NB * HN * NSEQ * NSEQ];     // 537 MB exp(scores) -> aw
__device__ float g_rowsum[NB * HN * NSEQ];

// ---------------- fast exp on the FMA pipe (avoid MUFU.EX2) ----------------
__device__ __forceinline__ float fast_exp(float x) {
    float t = x * 1.4426950408889634f;   // x * log2(e)
    float r = rintf(t);
    float f = t - r;                     // f in [-0.5, 0.5]
    float p =      1.5403530394e-4f;     // ln2^6/720
    p = fmaf(p, f, 1.3333558146e-3f);    // ln2^5/120
    p = fmaf(p, f, 9.6181291076e-3f);    // ln2^4/24
    p = fmaf(p, f, 5.5504108665e-2f);    // ln2^3/6
    p = fmaf(p, f, 2.4022650696e-1f);    // ln2^2/2
    p = fmaf(p, f, 6.9314718056e-1f);    // ln2
    p = fmaf(p, f, 1.0f);
    return p * __int_as_float(((int)r + 127) << 23);
}

// Load a 128-row x 32-col fp32 tile, transposed into smem as [k][row] with an
// XOR swizzle (k & 0x1C) so both the STS here and the LDS.128 in the mainloop
// are bank-conflict free. Global access is fully coalesced (128B per 8 lanes).
__device__ __forceinline__ void load_tile_T128x32(
    float* __restrict__ dst, const float* __restrict__ src, size_t stride, int tid)
{
#pragma unroll
    for (int s = 0; s < 4; s++) {
        int idx = tid + s * 256;
        int row = idx >> 3;
        int kq  = idx & 7;
        float4 v = *(const float4*)(src + (size_t)row * stride + kq * 4);
        int k   = kq * 4;          // swizzle value = k & 0x1C = k (k in {0,4,..,28})
        int col = row ^ k;
        dst[(k + 0) * 128 + col] = v.x;
        dst[(k + 1) * 128 + col] = v.y;
        dst[(k + 2) * 128 + col] = v.z;
        dst[(k + 3) * 128 + col] = v.w;
    }
}

// ---------------- generic C = A @ B^T, A[M,K], B[N,K] row-major ------------
__global__ void __launch_bounds__(256) sgemm_nt_kernel(
    const float* __restrict__ A, const float* __restrict__ Bm,
    float* __restrict__ C, int M, int N, int K, float alpha)
{
    __shared__ float As[32 * 128];
    __shared__ float Bs[32 * 128];
    const int tid = threadIdx.x;
    const int tx = tid & 15, ty = tid >> 4;
    const int m0 = blockIdx.y << 7, n0 = blockIdx.x << 7;
    const float* Ap = A + (size_t)m0 * K;
    const float* Bp = Bm + (size_t)n0 * K;
    float acc[8][8] = {};

    for (int k0 = 0; k0 < K; k0 += 32) {
        load_tile_T128x32(As, Ap + k0, K, tid);
        load_tile_T128x32(Bs, Bp + k0, K, tid);
        __syncthreads();
#pragma unroll
        for (int kk = 0; kk < 32; kk++) {
            const int swz = kk & 0x1C;
            float a[8], b[8];
            *(float4*)&a[0] = *(const float4*)&As[kk * 128 + ((ty * 8)     ^ swz)];
            *(float4*)&a[4] = *(const float4*)&As[kk * 128 + ((ty * 8 + 4) ^ swz)];
            *(float4*)&b[0] = *(const float4*)&Bs[kk * 128 + ((tx * 8)     ^ swz)];
            *(float4*)&b[4] = *(const float4*)&Bs[kk * 128 + ((tx * 8 + 4) ^ swz)];
#pragma unroll
            for (int i = 0; i < 8; i++)
#pragma unroll
                for (int j = 0; j < 8; j++)
                    acc[i][j] = fmaf(a[i], b[j], acc[i][j]);
        }
        __syncthreads();
    }
#pragma unroll
    for (int i = 0; i < 8; i++) {
        size_t off = (size_t)(m0 + ty * 8 + i) * N + n0 + tx * 8;
        float4 o;
        o.x = acc[i][0] * alpha; o.y = acc[i][1] * alpha;
        o.z = acc[i][2] * alpha; o.w = acc[i][3] * alpha;
        *(float4*)&C[off] = o;
        o.x = acc[i][4] * alpha; o.y = acc[i][5] * alpha;
        o.z = acc[i][6] * alpha; o.w = acc[i][7] * alpha;
        *(float4*)&C[off + 4] = o;
    }
}

// ------------- exp(QK^T) per head, with fused row-sum accumulation ---------
__global__ void __launch_bounds__(256) scores_kernel()
{
    __shared__ float Qs[32 * 128];
    __shared__ float Ks[32 * 128];
    const int tid = threadIdx.x;
    const int tx = tid & 15, ty = tid >> 4;
    const int bh = blockIdx.z;
    const int b = bh >> 4, h = bh & 15;
    const int i0 = blockIdx.y << 7, j0 = blockIdx.x << 7;
    const float* Qp = g_q  + (size_t)(b * NSEQ + i0) * DMODEL + h * HD;
    const float* Kp = g_kv + (size_t)(b * NSEQ + j0) * 2048   + h * HD;
    float acc[8][8] = {};

#pragma unroll
    for (int kc = 0; kc < HD; kc += 32) {
        load_tile_T128x32(Qs, Qp + kc, DMODEL, tid);
        load_tile_T128x32(Ks, Kp + kc, 2048, tid);
        __syncthreads();
#pragma unroll
        for (int kk = 0; kk < 32; kk++) {
            const int swz = kk & 0x1C;
            float a[8], bb[8];
            *(float4*)&a[0]  = *(const float4*)&Qs[kk * 128 + ((ty * 8)     ^ swz)];
            *(float4*)&a[4]  = *(const float4*)&Qs[kk * 128 + ((ty * 8 + 4) ^ swz)];
            *(float4*)&bb[0] = *(const float4*)&Ks[kk * 128 + ((tx * 8)     ^ swz)];
            *(float4*)&bb[4] = *(const float4*)&Ks[kk * 128 + ((tx * 8 + 4) ^ swz)];
#pragma unroll
            for (int i = 0; i < 8; i++)
#pragma unroll
                for (int j = 0; j < 8; j++)
                    acc[i][j] = fmaf(a[i], bb[j], acc[i][j]);
        }
        __syncthreads();
    }

    // epilogue: e = exp(s); store; per-row sums via shuffle + one atomic
    size_t ebase = ((size_t)bh * NSEQ + i0 + ty * 8) * NSEQ + j0 + tx * 8;
    const int rsbase = bh * NSEQ + i0 + ty * 8;
#pragma unroll
    for (int r = 0; r < 8; r++) {
        float e[8];
        float rs = 0.f;
#pragma unroll
        for (int c = 0; c < 8; c++) { e[c] = fast_exp(acc[r][c]); rs += e[c]; }
        *(float4*)&g_E[ebase + (size_t)r * NSEQ]     = make_float4(e[0], e[1], e[2], e[3]);
        *(float4*)&g_E[ebase + (size_t)r * NSEQ + 4] = make_float4(e[4], e[5], e[6], e[7]);
        rs += __shfl_down_sync(0xffffffffu, rs, 8, 16);
        rs += __shfl_down_sync(0xffffffffu, rs, 4, 16);
        rs += __shfl_down_sync(0xffffffffu, rs, 2, 16);
        rs += __shfl_down_sync(0xffffffffu, rs, 1, 16);
        if (tx == 0) atomicAdd(&g_rowsum[rsbase + r], rs);
    }
}

// ------ softmax-normalize + talking-heads mix + LayerNorm across heads -----
// In place on g_E. One thread = one (b, i, j-quad); all 16 head planes.
__global__ void __launch_bounds__(128) talkln_kernel(
    const float* __restrict__ Wtalk, const float* __restrict__ gamma,
    const float* __restrict__ beta)
{
    __shared__ float ws[256];
    __shared__ float rinv[16], gam[16], bet[16];
    const int tid = threadIdx.x;
    const int bi = blockIdx.y;
    const int b = bi >> 11, i = bi & 2047;
    const int j0 = (blockIdx.x << 9) + tid * 4;
    ws[tid]       = Wtalk[tid];
    ws[tid + 128] = Wtalk[tid + 128];
    if (tid < 16) {
        rinv[tid] = 1.0f / g_rowsum[(b * HN + tid) * NSEQ + i];
        gam[tid] = gamma[tid];
        bet[tid] = beta[tid];
    }
    __syncthreads();

    const size_t PL = (size_t)NSEQ * NSEQ;
    const size_t base0 = (size_t)(b * HN) * PL + (size_t)i * NSEQ + j0;

    float4 p[16], t[16];
#pragma unroll
    for (int h = 0; h < 16; h++) {
        float4 v = *(const float4*)&g_E[base0 + (size_t)h * PL];
        float s = rinv[h];
        p[h].x = v.x * s; p[h].y = v.y * s; p[h].z = v.z * s; p[h].w = v.w * s;
    }
#pragma unroll
    for (int g = 0; g < 16; g++) t[g] = make_float4(0.f, 0.f, 0.f, 0.f);
#pragma unroll
    for (int h = 0; h < 16; h++) {
#pragma unroll
        for (int g = 0; g < 16; g++) {
            float w = ws[g * 16 + h];
            t[g].x = fmaf(w, p[h].x, t[g].x);
            t[g].y = fmaf(w, p[h].y, t[g].y);
            t[g].z = fmaf(w, p[h].z, t[g].z);
            t[g].w = fmaf(w, p[h].w, t[g].w);
        }
    }
    float4 mu = make_float4(0.f, 0.f, 0.f, 0.f);
#pragma unroll
    for (int g = 0; g < 16; g++) {
        mu.x += t[g].x; mu.y += t[g].y; mu.z += t[g].z; mu.w += t[g].w;
    }
    const float inv16 = 1.0f / 16.0f;
    mu.x *= inv16; mu.y *= inv16; mu.z *= inv16; mu.w *= inv16;
    float4 m2 = make_float4(0.f, 0.f, 0.f, 0.f);
#pragma unroll
    for (int g = 0; g < 16; g++) {
        float dx = t[g].x - mu.x, dy = t[g].y - mu.y;
        float dz = t[g].z - mu.z, dw = t[g].w - mu.w;
        m2.x = fmaf(dx, dx, m2.x); m2.y = fmaf(dy, dy, m2.y);
        m2.z = fmaf(dz, dz, m2.z); m2.w = fmaf(dw, dw, m2.w);
    }
    float4 rs;
    rs.x = rsqrtf(m2.x * inv16 + LN_EPS);
    rs.y = rsqrtf(m2.y * inv16 + LN_EPS);
    rs.z = rsqrtf(m2.z * inv16 + LN_EPS);
    rs.w = rsqrtf(m2.w * inv16 + LN_EPS);
#pragma unroll
    for (int g = 0; g < 16; g++) {
        float gg = gam[g], bb = bet[g];
        float4 o;
        o.x = fmaf((t[g].x - mu.x) * rs.x, gg, bb);
        o.y = fmaf((t[g].y - mu.y) * rs.y, gg, bb);
        o.z = fmaf((t[g].z - mu.z) * rs.z, gg, bb);
        o.w = fmaf((t[g].w - mu.w) * rs.w, gg, bb);
        *(float4*)&g_E[base0 + (size_t)g * PL] = o;
    }
}

// --------------------- out[b,i,g*64+d] = sum_j aw * v ----------------------
__global__ void __launch_bounds__(256) pv_kernel(float* __restrict__ out)
{
    __shared__ float As[32 * 128];
    __shared__ float Bs[32 * 64];
    const int tid = threadIdx.x;
    const int tx = tid & 15, ty = tid >> 4;
    const int bh = blockIdx.y;
    const int b = bh >> 4, g = bh & 15;
    const int i0 = blockIdx.x << 7;
    const float* Vp = g_kv + (size_t)(b * NSEQ) * 2048 + 1024 + g * HD;
    const size_t Abase = ((size_t)bh * NSEQ + i0) * NSEQ;
    float acc[8][4] = {};

    for (int k0 = 0; k0 < NSEQ; k0 += 32) {
        load_tile_T128x32(As, g_E + Abase + k0, NSEQ, tid);
#pragma unroll
        for (int s = 0; s < 2; s++) {
            int idx = tid + s * 256;
            int row = idx >> 4, dq = idx & 15;
            *(float4*)&Bs[row * 64 + dq * 4] =
                *(const float4*)&Vp[(size_t)(k0 + row) * 2048 + dq * 4];
        }
        __syncthreads();
#pragma unroll
        for (int kk = 0; kk < 32; kk++) {
            const int swz = kk & 0x1C;
            float a[8];
            *(float4*)&a[0] = *(const float4*)&As[kk * 128 + ((ty * 8)     ^ swz)];
            *(float4*)&a[4] = *(const float4*)&As[kk * 128 + ((ty * 8 + 4) ^ swz)];
            float4 bv = *(const float4*)&Bs[kk * 64 + tx * 4];
#pragma unroll
            for (int i = 0; i < 8; i++) {
                acc[i][0] = fmaf(a[i], bv.x, acc[i][0]);
                acc[i][1] = fmaf(a[i], bv.y, acc[i][1]);
                acc[i][2] = fmaf(a[i], bv.z, acc[i][2]);
                acc[i][3] = fmaf(a[i], bv.w, acc[i][3]);
            }
        }
        __syncthreads();
    }
#pragma unroll
    for (int r = 0; r < 8; r++) {
        size_t off = (size_t)(b * NSEQ + i0 + ty * 8 + r) * DMODEL + g * HD + tx * 4;
        *(float4*)&out[off] = make_float4(acc[r][0], acc[r][1], acc[r][2], acc[r][3]);
    }
}

__global__ void zero_rowsum_kernel()
{
    int i = blockIdx.x * 256 + threadIdx.x;
    if (i < NB * HN * NSEQ) g_rowsum[i] = 0.f;
}

// ---------------------------------------------------------------------------
extern "C" void kernel_launch(void* const* d_in, const int* in_sizes, int n_in,
                              void* d_out, int out_size)
{
    const float* x       = (const float*)d_in[0];
    const float* context = (const float*)d_in[1];
    const float* Wq      = (const float*)d_in[2];
    const float* Wkv     = (const float*)d_in[3];
    const float* Wtalk   = (const float*)d_in[4];
    const float* gamma   = (const float*)d_in[5];
    const float* beta    = (const float*)d_in[6];
    float* out = (float*)d_out;

    float *qp, *kvp;
    cudaGetSymbolAddress((void**)&qp, g_q);
    cudaGetSymbolAddress((void**)&kvp, g_kv);

    zero_rowsum_kernel<<<(NB * HN * NSEQ + 255) / 256, 256>>>();

    // q = x @ Wq^T, pre-scaled by head_dim^-0.5
    sgemm_nt_kernel<<<dim3(DMODEL / 128, (NB * NSEQ) / 128), 256>>>(
        x, Wq, qp, NB * NSEQ, DMODEL, DMODEL, 0.125f);

    // kv = context @ Wkv^T  (cols 0..1023 = k, 1024..2047 = v)
    sgemm_nt_kernel<<<dim3(2048 / 128, (NB * NSEQ) / 128), 256>>>(
        context, Wkv, kvp, NB * NSEQ, 2048, DMODEL, 1.0f);

    // exp(q k^T) per head + row sums
    scores_kernel<<<dim3(NSEQ / 128, NSEQ / 128, NB * HN), 256>>>();

    // softmax-normalize + talking heads + LN across heads (in place)
    talkln_kernel<<<dim3(4, NB * NSEQ), 128>>>(Wtalk, gamma, beta);

    // attn = aw @ v, written directly in final [b, n, h*d] layout
    pv_kernel<<<dim3(NSEQ / 128, NB * HN), 256>>>(out);
}

// round 2
// speedup vs baseline: 1.0353x; 1.0353x over previous
#include <cuda_runtime.h>
#include <cstdint>
#include <cstddef>

#define HN     16
#define DMODEL 1024
#define NSEQ   2048
#define NB     2
#define HD     64
#define LN_EPS 1e-5f

typedef unsigned long long u64;

// ---------------- scratch (device globals; no allocation allowed) ----------
__device__ float g_q [(size_t)NB * NSEQ * DMODEL];        // 16.8 MB
__device__ float g_kv[(size_t)NB * NSEQ * 2048];          // 33.5 MB (k | v)
__device__ float g_E [(size_t)NB * HN * NSEQ * NSEQ];     // 537 MB exp(scores) -> aw
__device__ float g_rowsum[NB * HN * NSEQ];

// -------------------- packed f32x2 helpers (Blackwell FFMA2) ---------------
__device__ __forceinline__ u64 bcast2(float x) {
    u64 r;
    unsigned u = __float_as_uint(x);
    asm("mov.b64 %0, {%1, %1};" : "=l"(r) : "r"(u));
    return r;
}
__device__ __forceinline__ void fma2(u64& d, u64 a, u64 b) {
    asm("fma.rn.f32x2 %0, %1, %2, %0;" : "+l"(d) : "l"(a), "l"(b));
}

// ---------------- fast exp on the FMA pipe (avoid MUFU.EX2) ----------------
__device__ __forceinline__ float fast_exp(float x) {
    float t = x * 1.4426950408889634f;   // x * log2(e)
    float r = rintf(t);
    float f = t - r;                     // f in [-0.5, 0.5]
    float p =      1.5403530394e-4f;     // ln2^6/720
    p = fmaf(p, f, 1.3333558146e-3f);    // ln2^5/120
    p = fmaf(p, f, 9.6181291076e-3f);    // ln2^4/24
    p = fmaf(p, f, 5.5504108665e-2f);    // ln2^3/6
    p = fmaf(p, f, 2.4022650696e-1f);    // ln2^2/2
    p = fmaf(p, f, 6.9314718056e-1f);    // ln2
    p = fmaf(p, f, 1.0f);
    return p * __int_as_float(((int)r + 127) << 23);
}

// Load a 128-row x 32-col fp32 tile, transposed into smem as [k][row] with an
// XOR swizzle (k & 0x1C) so STS here and LDS.128 in the mainloop are
// bank-conflict free. Global access is fully coalesced.
__device__ __forceinline__ void load_tile_T128x32(
    float* __restrict__ dst, const float* __restrict__ src, size_t stride, int tid)
{
#pragma unroll
    for (int s = 0; s < 4; s++) {
        int idx = tid + s * 256;
        int row = idx >> 3;
        int kq  = idx & 7;
        float4 v = *(const float4*)(src + (size_t)row * stride + kq * 4);
        int k   = kq * 4;
        int col = row ^ k;
        dst[(k + 0) * 128 + col] = v.x;
        dst[(k + 1) * 128 + col] = v.y;
        dst[(k + 2) * 128 + col] = v.z;
        dst[(k + 3) * 128 + col] = v.w;
    }
}

// 128x128-tile inner product step on packed pairs: acc[8][4] u64 pairs (j dim)
__device__ __forceinline__ void mma_step_128x128(
    const float* __restrict__ As, const float* __restrict__ Bs,
    int ty, int tx, u64 (&acc)[8][4])
{
#pragma unroll
    for (int kk = 0; kk < 32; kk++) {
        const int swz = kk & 0x1C;
        float a[8];
        u64 b2[4];
        *(float4*)&a[0]  = *(const float4*)&As[kk * 128 + ((ty * 8)     ^ swz)];
        *(float4*)&a[4]  = *(const float4*)&As[kk * 128 + ((ty * 8 + 4) ^ swz)];
        *(float4*)&b2[0] = *(const float4*)&Bs[kk * 128 + ((tx * 8)     ^ swz)];
        *(float4*)&b2[2] = *(const float4*)&Bs[kk * 128 + ((tx * 8 + 4) ^ swz)];
        u64 a2[8];
#pragma unroll
        for (int i = 0; i < 8; i++) a2[i] = bcast2(a[i]);
#pragma unroll
        for (int i = 0; i < 8; i++)
#pragma unroll
            for (int j = 0; j < 4; j++)
                fma2(acc[i][j], a2[i], b2[j]);
    }
}

// ---------------- generic C = A @ B^T, A[M,K], B[N,K] row-major ------------
__global__ void __launch_bounds__(256) sgemm_nt_kernel(
    const float* __restrict__ A, const float* __restrict__ Bm,
    float* __restrict__ C, int M, int N, int K, float alpha)
{
    __shared__ float As[32 * 128];
    __shared__ float Bs[32 * 128];
    const int tid = threadIdx.x;
    const int tx = tid & 15, ty = tid >> 4;
    const int m0 = blockIdx.y << 7, n0 = blockIdx.x << 7;
    const float* Ap = A + (size_t)m0 * K;
    const float* Bp = Bm + (size_t)n0 * K;
    u64 acc[8][4] = {};

    for (int k0 = 0; k0 < K; k0 += 32) {
        load_tile_T128x32(As, Ap + k0, K, tid);
        load_tile_T128x32(Bs, Bp + k0, K, tid);
        __syncthreads();
        mma_step_128x128(As, Bs, ty, tx, acc);
        __syncthreads();
    }
    const float* accf = (const float*)acc;
#pragma unroll
    for (int i = 0; i < 8; i++) {
        size_t off = (size_t)(m0 + ty * 8 + i) * N + n0 + tx * 8;
        float4 o;
        o.x = accf[i * 8 + 0] * alpha; o.y = accf[i * 8 + 1] * alpha;
        o.z = accf[i * 8 + 2] * alpha; o.w = accf[i * 8 + 3] * alpha;
        *(float4*)&C[off] = o;
        o.x = accf[i * 8 + 4] * alpha; o.y = accf[i * 8 + 5] * alpha;
        o.z = accf[i * 8 + 6] * alpha; o.w = accf[i * 8 + 7] * alpha;
        *(float4*)&C[off + 4] = o;
    }
}

// ------------- exp(QK^T) per head, with fused row-sum accumulation ---------
__global__ void __launch_bounds__(256) scores_kernel()
{
    __shared__ float Qs[32 * 128];
    __shared__ float Ks[32 * 128];
    const int tid = threadIdx.x;
    const int tx = tid & 15, ty = tid >> 4;
    const int bh = blockIdx.z;
    const int b = bh >> 4, h = bh & 15;
    const int i0 = blockIdx.y << 7, j0 = blockIdx.x << 7;
    const float* Qp = g_q  + (size_t)(b * NSEQ + i0) * DMODEL + h * HD;
    const float* Kp = g_kv + (size_t)(b * NSEQ + j0) * 2048   + h * HD;
    u64 acc[8][4] = {};

#pragma unroll
    for (int kc = 0; kc < HD; kc += 32) {
        load_tile_T128x32(Qs, Qp + kc, DMODEL, tid);
        load_tile_T128x32(Ks, Kp + kc, 2048, tid);
        __syncthreads();
        mma_step_128x128(Qs, Ks, ty, tx, acc);
        __syncthreads();
    }

    // epilogue: e = exp(s); store; per-row sums via shuffle + one atomic
    const float* accf = (const float*)acc;
    size_t ebase = ((size_t)bh * NSEQ + i0 + ty * 8) * NSEQ + j0 + tx * 8;
    const int rsbase = bh * NSEQ + i0 + ty * 8;
#pragma unroll
    for (int r = 0; r < 8; r++) {
        float e[8];
        float rs = 0.f;
#pragma unroll
        for (int c = 0; c < 8; c++) { e[c] = fast_exp(accf[r * 8 + c]); rs += e[c]; }
        *(float4*)&g_E[ebase + (size_t)r * NSEQ]     = make_float4(e[0], e[1], e[2], e[3]);
        *(float4*)&g_E[ebase + (size_t)r * NSEQ + 4] = make_float4(e[4], e[5], e[6], e[7]);
        rs += __shfl_down_sync(0xffffffffu, rs, 8, 16);
        rs += __shfl_down_sync(0xffffffffu, rs, 4, 16);
        rs += __shfl_down_sync(0xffffffffu, rs, 2, 16);
        rs += __shfl_down_sync(0xffffffffu, rs, 1, 16);
        if (tx == 0) atomicAdd(&g_rowsum[rsbase + r], rs);
    }
}

// ------ softmax-normalize + talking-heads mix + LayerNorm across heads -----
// In place on g_E. One thread = one (b, i, j-quad); all 16 head planes.
__global__ void __launch_bounds__(128) talkln_kernel(
    const float* __restrict__ Wtalk, const float* __restrict__ gamma,
    const float* __restrict__ beta)
{
    __shared__ float ws[256];
    __shared__ float rinv[16], gam[16], bet[16];
    const int tid = threadIdx.x;
    const int bi = blockIdx.y;
    const int b = bi >> 11, i = bi & 2047;
    const int j0 = (blockIdx.x << 9) + tid * 4;
    ws[tid]       = Wtalk[tid];
    ws[tid + 128] = Wtalk[tid + 128];
    if (tid < 16) {
        rinv[tid] = 1.0f / g_rowsum[(b * HN + tid) * NSEQ + i];
        gam[tid] = gamma[tid];
        bet[tid] = beta[tid];
    }
    __syncthreads();

    const size_t PL = (size_t)NSEQ * NSEQ;
    const size_t base0 = (size_t)(b * HN) * PL + (size_t)i * NSEQ + j0;

    u64 p2[16][2];
    u64 t2[16][2] = {};
#pragma unroll
    for (int h = 0; h < 16; h++) {
        float4 v = *(const float4*)&g_E[base0 + (size_t)h * PL];
        float s = rinv[h];
        v.x *= s; v.y *= s; v.z *= s; v.w *= s;
        *(float4*)&p2[h][0] = v;
    }
#pragma unroll
    for (int h = 0; h < 16; h++) {
#pragma unroll
        for (int g = 0; g < 16; g++) {
            u64 w2 = bcast2(ws[g * 16 + h]);
            fma2(t2[g][0], w2, p2[h][0]);
            fma2(t2[g][1], w2, p2[h][1]);
        }
    }
    float4 t[16];
#pragma unroll
    for (int g = 0; g < 16; g++) t[g] = *(const float4*)&t2[g][0];

    float4 mu = make_float4(0.f, 0.f, 0.f, 0.f);
#pragma unroll
    for (int g = 0; g < 16; g++) {
        mu.x += t[g].x; mu.y += t[g].y; mu.z += t[g].z; mu.w += t[g].w;
    }
    const float inv16 = 1.0f / 16.0f;
    mu.x *= inv16; mu.y *= inv16; mu.z *= inv16; mu.w *= inv16;
    float4 m2 = make_float4(0.f, 0.f, 0.f, 0.f);
#pragma unroll
    for (int g = 0; g < 16; g++) {
        float dx = t[g].x - mu.x, dy = t[g].y - mu.y;
        float dz = t[g].z - mu.z, dw = t[g].w - mu.w;
        m2.x = fmaf(dx, dx, m2.x); m2.y = fmaf(dy, dy, m2.y);
        m2.z = fmaf(dz, dz, m2.z); m2.w = fmaf(dw, dw, m2.w);
    }
    float4 rs;
    rs.x = rsqrtf(m2.x * inv16 + LN_EPS);
    rs.y = rsqrtf(m2.y * inv16 + LN_EPS);
    rs.z = rsqrtf(m2.z * inv16 + LN_EPS);
    rs.w = rsqrtf(m2.w * inv16 + LN_EPS);
#pragma unroll
    for (int g = 0; g < 16; g++) {
        float gg = gam[g], bb = bet[g];
        float4 o;
        o.x = fmaf((t[g].x - mu.x) * rs.x, gg, bb);
        o.y = fmaf((t[g].y - mu.y) * rs.y, gg, bb);
        o.z = fmaf((t[g].z - mu.z) * rs.z, gg, bb);
        o.w = fmaf((t[g].w - mu.w) * rs.w, gg, bb);
        *(float4*)&g_E[base0 + (size_t)g * PL] = o;
    }
}

// --------------------- out[b,i,g*64+d] = sum_j aw * v ----------------------
__global__ void __launch_bounds__(256) pv_kernel(float* __restrict__ out)
{
    __shared__ float As[32 * 128];
    __shared__ float Bs[32 * 64];
    const int tid = threadIdx.x;
    const int tx = tid & 15, ty = tid >> 4;
    const int bh = blockIdx.y;
    const int b = bh >> 4, g = bh & 15;
    const int i0 = blockIdx.x << 7;
    const float* Vp = g_kv + (size_t)(b * NSEQ) * 2048 + 1024 + g * HD;
    const size_t Abase = ((size_t)bh * NSEQ + i0) * NSEQ;
    u64 acc[8][2] = {};

    for (int k0 = 0; k0 < NSEQ; k0 += 32) {
        load_tile_T128x32(As, g_E + Abase + k0, NSEQ, tid);
#pragma unroll
        for (int s = 0; s < 2; s++) {
            int idx = tid + s * 256;
            int row = idx >> 4, dq = idx & 15;
            *(float4*)&Bs[row * 64 + dq * 4] =
                *(const float4*)&Vp[(size_t)(k0 + row) * 2048 + dq * 4];
        }
        __syncthreads();
#pragma unroll
        for (int kk = 0; kk < 32; kk++) {
            const int swz = kk & 0x1C;
            float a[8];
            u64 b2[2];
            *(float4*)&a[0]  = *(const float4*)&As[kk * 128 + ((ty * 8)     ^ swz)];
            *(float4*)&a[4]  = *(const float4*)&As[kk * 128 + ((ty * 8 + 4) ^ swz)];
            *(float4*)&b2[0] = *(const float4*)&Bs[kk * 64 + tx * 4];
            u64 a2[8];
#pragma unroll
            for (int i = 0; i < 8; i++) a2[i] = bcast2(a[i]);
#pragma unroll
            for (int i = 0; i < 8; i++) {
                fma2(acc[i][0], a2[i], b2[0]);
                fma2(acc[i][1], a2[i], b2[1]);
            }
        }
        __syncthreads();
    }
    const float* accf = (const float*)acc;
#pragma unroll
    for (int r = 0; r < 8; r++) {
        size_t off = (size_t)(b * NSEQ + i0 + ty * 8 + r) * DMODEL + g * HD + tx * 4;
        *(float4*)&out[off] =
            make_float4(accf[r * 4 + 0], accf[r * 4 + 1], accf[r * 4 + 2], accf[r * 4 + 3]);
    }
}

__global__ void zero_rowsum_kernel()
{
    int i = blockIdx.x * 256 + threadIdx.x;
    if (i < NB * HN * NSEQ) g_rowsum[i] = 0.f;
}

// ---------------------------------------------------------------------------
extern "C" void kernel_launch(void* const* d_in, const int* in_sizes, int n_in,
                              void* d_out, int out_size)
{
    const float* x       = (const float*)d_in[0];
    const float* context = (const float*)d_in[1];
    const float* Wq      = (const float*)d_in[2];
    const float* Wkv     = (const float*)d_in[3];
    const float* Wtalk   = (const float*)d_in[4];
    const float* gamma   = (const float*)d_in[5];
    const float* beta    = (const float*)d_in[6];
    float* out = (float*)d_out;

    float *qp, *kvp;
    cudaGetSymbolAddress((void**)&qp, g_q);
    cudaGetSymbolAddress((void**)&kvp, g_kv);

    zero_rowsum_kernel<<<(NB * HN * NSEQ + 255) / 256, 256>>>();

    // q = x @ Wq^T, pre-scaled by head_dim^-0.5
    sgemm_nt_kernel<<<dim3(DMODEL / 128, (NB * NSEQ) / 128), 256>>>(
        x, Wq, qp, NB * NSEQ, DMODEL, DMODEL, 0.125f);

    // kv = context @ Wkv^T  (cols 0..1023 = k, 1024..2047 = v)
    sgemm_nt_kernel<<<dim3(2048 / 128, (NB * NSEQ) / 128), 256>>>(
        context, Wkv, kvp, NB * NSEQ, 2048, DMODEL, 1.0f);

    // exp(q k^T) per head + row sums
    scores_kernel<<<dim3(NSEQ / 128, NSEQ / 128, NB * HN), 256>>>();

    // softmax-normalize + talking heads + LN across heads (in place)
    talkln_kernel<<<dim3(4, NB * NSEQ), 128>>>(Wtalk, gamma, beta);

    // attn = aw @ v, written directly in final [b, n, h*d] layout
    pv_kernel<<<dim3(NSEQ / 128, NB * HN), 256>>>(out);
}

// round 4
// speedup vs baseline: 1.6694x; 1.6125x over previous
#include <cuda_runtime.h>
#include <cuda_bf16.h>
#include <cstdint>
#include <cstddef>

#define HN     16
#define DMODEL 1024
#define NSEQ   2048
#define NB     2
#define HD     64
#define LN_EPS 1e-5f

typedef unsigned long long u64;

// ---------------- scratch (device globals; no allocation allowed) ----------
__device__ float g_q [(size_t)NB * NSEQ * DMODEL];        // 16.8 MB
__device__ float g_kv[(size_t)NB * NSEQ * 2048];          // 33.5 MB (k | v)
__device__ float g_vt[(size_t)NB * DMODEL * NSEQ];        // 16.8 MB v transposed
__device__ float g_E [(size_t)NB * HN * NSEQ * NSEQ];     // 537 MB exp(scores) -> aw
__device__ float g_rowsum[NB * HN * NSEQ];

// -------------------- packed f32x2 helpers (talkln) ------------------------
__device__ __forceinline__ u64 bcast2(float x) {
    u64 r;
    unsigned u = __float_as_uint(x);
    asm("mov.b64 %0, {%1, %1};" : "=l"(r) : "r"(u));
    return r;
}
__device__ __forceinline__ void fma2(u64& d, u64 a, u64 b) {
    asm("fma.rn.f32x2 %0, %1, %2, %0;" : "+l"(d) : "l"(a), "l"(b));
}

// ---------------- fast exp on the FMA pipe (avoid MUFU.EX2) ----------------
__device__ __forceinline__ float fast_exp(float x) {
    float t = x * 1.4426950408889634f;
    float r = rintf(t);
    float f = t - r;
    float p =      1.5403530394e-4f;
    p = fmaf(p, f, 1.3333558146e-3f);
    p = fmaf(p, f, 9.6181291076e-3f);
    p = fmaf(p, f, 5.5504108665e-2f);
    p = fmaf(p, f, 2.4022650696e-1f);
    p = fmaf(p, f, 6.9314718056e-1f);
    p = fmaf(p, f, 1.0f);
    return p * __int_as_float(((int)r + 127) << 23);
}

// ------------------------- mma.sync bf16 wrapper ----------------------------
__device__ __forceinline__ void mma16816(
    float (&c)[4], const uint32_t (&a)[4], uint32_t b0, uint32_t b1)
{
    asm volatile(
        "mma.sync.aligned.m16n8k16.row.col.f32.bf16.bf16.f32 "
        "{%0,%1,%2,%3}, {%4,%5,%6,%7}, {%8,%9}, {%0,%1,%2,%3};"
        : "+f"(c[0]), "+f"(c[1]), "+f"(c[2]), "+f"(c[3])
        : "r"(a[0]), "r"(a[1]), "r"(a[2]), "r"(a[3]), "r"(b0), "r"(b1));
}
__device__ __forceinline__ uint32_t lds32(const uint16_t* p, int off) {
    return *(const uint32_t*)(p + off);
}

// Stage ROWS x 32 fp32 tile as bf16 hi/lo splits, row-major, stride 36 elems.
template<int ROWS>
__device__ __forceinline__ void stage_split(
    uint16_t* __restrict__ hi, uint16_t* __restrict__ lo,
    const float* __restrict__ src, size_t stride, int tid)
{
#pragma unroll
    for (int s = 0; s < ROWS / 32; s++) {
        int idx = s * 256 + tid;
        int row = idx >> 3;
        int cg  = idx & 7;
        float4 v = *(const float4*)(src + (size_t)row * stride + cg * 4);
        __nv_bfloat162 h01 = __floats2bfloat162_rn(v.x, v.y);
        __nv_bfloat162 h23 = __floats2bfloat162_rn(v.z, v.w);
        float rx = v.x - __bfloat162float(__low2bfloat16(h01));
        float ry = v.y - __bfloat162float(__high2bfloat16(h01));
        float rz = v.z - __bfloat162float(__low2bfloat16(h23));
        float rw = v.w - __bfloat162float(__high2bfloat16(h23));
        __nv_bfloat162 l01 = __floats2bfloat162_rn(rx, ry);
        __nv_bfloat162 l23 = __floats2bfloat162_rn(rz, rw);
        int off = row * 36 + cg * 4;
        *(uint2*)(hi + off) = make_uint2(*(uint32_t*)&h01, *(uint32_t*)&h23);
        *(uint2*)(lo + off) = make_uint2(*(uint32_t*)&l01, *(uint32_t*)&l23);
    }
}

// ---- HMMA split-bf16 core: C[128 x NT] = A[128,K] @ B[NT,K]^T  (NT 64/128) -
// 256 threads = 8 warps (4 x 2). Warp tile 32 x (NT/2). K-chunk 32.
template<int NT, bool EXP_EPI>
__device__ __forceinline__ void hmma_core(
    const float* __restrict__ A, size_t lda,
    const float* __restrict__ B, size_t ldb,
    int nk, float* __restrict__ C, size_t ldc,
    float alpha, float* __restrict__ rowsum)
{
    constexpr int NTILES = NT / 16;              // n-tiles per warp (8 wide)
    __shared__ __align__(16) uint16_t sAhi[128 * 36];
    __shared__ __align__(16) uint16_t sAlo[128 * 36];
    __shared__ __align__(16) uint16_t sBhi[NT * 36];
    __shared__ __align__(16) uint16_t sBlo[NT * 36];

    const int tid  = threadIdx.x;
    const int wid  = tid >> 5;
    const int lane = tid & 31;
    const int wm = wid & 3, wn = wid >> 2;       // 4 x 2 warp grid
    const int g = lane >> 2, t = lane & 3;

    float acc[2][NTILES][4];
#pragma unroll
    for (int mt = 0; mt < 2; mt++)
#pragma unroll
        for (int nt = 0; nt < NTILES; nt++)
#pragma unroll
            for (int q = 0; q < 4; q++) acc[mt][nt][q] = 0.f;

    for (int i = 0; i < nk; i++) {
        __syncthreads();
        stage_split<128>(sAhi, sAlo, A + (size_t)i * 32, lda, tid);
        stage_split<NT >(sBhi, sBlo, B + (size_t)i * 32, ldb, tid);
        __syncthreads();
#pragma unroll
        for (int ks = 0; ks < 2; ks++) {
            uint32_t ah[2][4], al[2][4];
#pragma unroll
            for (int mt = 0; mt < 2; mt++) {
                int r0 = (wm * 32 + mt * 16 + g) * 36 + ks * 16 + 2 * t;
                ah[mt][0] = lds32(sAhi, r0);
                ah[mt][1] = lds32(sAhi, r0 + 8 * 36);
                ah[mt][2] = lds32(sAhi, r0 + 8);
                ah[mt][3] = lds32(sAhi, r0 + 8 * 36 + 8);
                al[mt][0] = lds32(sAlo, r0);
                al[mt][1] = lds32(sAlo, r0 + 8 * 36);
                al[mt][2] = lds32(sAlo, r0 + 8);
                al[mt][3] = lds32(sAlo, r0 + 8 * 36 + 8);
            }
#pragma unroll
            for (int nt = 0; nt < NTILES; nt++) {
                int c0 = (wn * (NT / 2) + nt * 8 + g) * 36 + ks * 16 + 2 * t;
                uint32_t bh0 = lds32(sBhi, c0), bh1 = lds32(sBhi, c0 + 8);
                uint32_t bl0 = lds32(sBlo, c0), bl1 = lds32(sBlo, c0 + 8);
#pragma unroll
                for (int mt = 0; mt < 2; mt++) {
                    mma16816(acc[mt][nt], ah[mt], bh0, bh1);
                    mma16816(acc[mt][nt], ah[mt], bl0, bl1);
                    mma16816(acc[mt][nt], al[mt], bh0, bh1);
                }
            }
        }
    }

    // epilogue: thread holds rows {R, R+8}, cols ncol+2t(+1) per ntile
#pragma unroll
    for (int mt = 0; mt < 2; mt++) {
        int r0 = wm * 32 + mt * 16 + g;
        float rs0 = 0.f, rs1 = 0.f;
#pragma unroll
        for (int nt = 0; nt < NTILES; nt++) {
            int col = wn * (NT / 2) + nt * 8 + 2 * t;
            float2 lo_pair, hi_pair;
            if (EXP_EPI) {
                lo_pair.x = fast_exp(acc[mt][nt][0]);
                lo_pair.y = fast_exp(acc[mt][nt][1]);
                hi_pair.x = fast_exp(acc[mt][nt][2]);
                hi_pair.y = fast_exp(acc[mt][nt][3]);
                rs0 += lo_pair.x + lo_pair.y;
                rs1 += hi_pair.x + hi_pair.y;
            } else {
                lo_pair.x = acc[mt][nt][0] * alpha;
                lo_pair.y = acc[mt][nt][1] * alpha;
                hi_pair.x = acc[mt][nt][2] * alpha;
                hi_pair.y = acc[mt][nt][3] * alpha;
            }
            *(float2*)(C + (size_t)r0 * ldc + col)       = lo_pair;
            *(float2*)(C + (size_t)(r0 + 8) * ldc + col) = hi_pair;
        }
        if (EXP_EPI) {
            rs0 += __shfl_down_sync(0xffffffffu, rs0, 1, 4);
            rs0 += __shfl_down_sync(0xffffffffu, rs0, 2, 4);
            rs1 += __shfl_down_sync(0xffffffffu, rs1, 1, 4);
            rs1 += __shfl_down_sync(0xffffffffu, rs1, 2, 4);
            if (t == 0) {
                atomicAdd(&rowsum[r0], rs0);
                atomicAdd(&rowsum[r0 + 8], rs1);
            }
        }
    }
}

// ------------------------------- wrappers ----------------------------------
__global__ void __launch_bounds__(256) gemm_hmma_kernel(
    const float* __restrict__ A, const float* __restrict__ B,
    float* __restrict__ C, int N, float alpha)
{
    int m0 = blockIdx.y << 7, n0 = blockIdx.x << 7;
    hmma_core<128, false>(A + (size_t)m0 * DMODEL, DMODEL,
                          B + (size_t)n0 * DMODEL, DMODEL, DMODEL / 32,
                          C + (size_t)m0 * N + n0, (size_t)N, alpha, nullptr);
}

__global__ void __launch_bounds__(256) scores_hmma_kernel()
{
    int bh = blockIdx.z, b = bh >> 4, h = bh & 15;
    int i0 = blockIdx.y << 7, j0 = blockIdx.x << 7;
    const float* Ap = g_q  + ((size_t)(b * NSEQ + i0)) * DMODEL + h * HD;
    const float* Bp = g_kv + ((size_t)(b * NSEQ + j0)) * 2048   + h * HD;
    float* Cb = g_E + (size_t)bh * NSEQ * NSEQ + (size_t)i0 * NSEQ + j0;
    hmma_core<128, true>(Ap, DMODEL, Bp, 2048, HD / 32, Cb, NSEQ, 1.f,
                         g_rowsum + bh * NSEQ + i0);
}

__global__ void __launch_bounds__(256) pv_hmma_kernel(float* __restrict__ out)
{
    int bg = blockIdx.y, b = bg >> 4, g = bg & 15;
    int i0 = blockIdx.x << 7;
    const float* Ap = g_E + (size_t)bg * NSEQ * NSEQ + (size_t)i0 * NSEQ;
    const float* Bp = g_vt + ((size_t)b * DMODEL + g * HD) * NSEQ;
    float* Cb = out + ((size_t)(b * NSEQ + i0)) * DMODEL + g * HD;
    hmma_core<64, false>(Ap, NSEQ, Bp, NSEQ, NSEQ / 32, Cb, DMODEL, 1.f, nullptr);
}

// ------------------- transpose v: [b][j][c] -> [b][c][j] --------------------
__global__ void __launch_bounds__(256) transpose_v_kernel()
{
    __shared__ float t[32][33];
    int j0 = blockIdx.x << 5, c0 = blockIdx.y << 5, b = blockIdx.z;
    int tx = threadIdx.x, ty = threadIdx.y;
#pragma unroll
    for (int i = 0; i < 4; i++)
        t[ty + i * 8][tx] =
            g_kv[((size_t)(b * NSEQ) + j0 + ty + i * 8) * 2048 + 1024 + c0 + tx];
    __syncthreads();
#pragma unroll
    for (int i = 0; i < 4; i++)
        g_vt[((size_t)b * DMODEL + c0 + ty + i * 8) * NSEQ + j0 + tx] =
            t[tx][ty + i * 8];
}

// ------ softmax-normalize + talking-heads mix + LayerNorm across heads -----
__global__ void __launch_bounds__(128) talkln_kernel(
    const float* __restrict__ Wtalk, const float* __restrict__ gamma,
    const float* __restrict__ beta)
{
    __shared__ float ws[256];
    __shared__ float rinv[16], gam[16], bet[16];
    const int tid = threadIdx.x;
    const int bi = blockIdx.y;
    const int b = bi >> 11, i = bi & 2047;
    const int j0 = (blockIdx.x << 9) + tid * 4;
    ws[tid]       = Wtalk[tid];
    ws[tid + 128] = Wtalk[tid + 128];
    if (tid < 16) {
        rinv[tid] = 1.0f / g_rowsum[(b * HN + tid) * NSEQ + i];
        gam[tid] = gamma[tid];
        bet[tid] = beta[tid];
    }
    __syncthreads();

    const size_t PL = (size_t)NSEQ * NSEQ;
    const size_t base0 = (size_t)(b * HN) * PL + (size_t)i * NSEQ + j0;

    u64 p2[16][2];
    u64 t2[16][2] = {};
#pragma unroll
    for (int h = 0; h < 16; h++) {
        float4 v = *(const float4*)&g_E[base0 + (size_t)h * PL];
        float s = rinv[h];
        v.x *= s; v.y *= s; v.z *= s; v.w *= s;
        *(float4*)&p2[h][0] = v;
    }
#pragma unroll
    for (int h = 0; h < 16; h++) {
#pragma unroll
        for (int g = 0; g < 16; g++) {
            u64 w2 = bcast2(ws[g * 16 + h]);
            fma2(t2[g][0], w2, p2[h][0]);
            fma2(t2[g][1], w2, p2[h][1]);
        }
    }
    float4 t[16];
#pragma unroll
    for (int g = 0; g < 16; g++) t[g] = *(const float4*)&t2[g][0];

    float4 mu = make_float4(0.f, 0.f, 0.f, 0.f);
#pragma unroll
    for (int g = 0; g < 16; g++) {
        mu.x += t[g].x; mu.y += t[g].y; mu.z += t[g].z; mu.w += t[g].w;
    }
    const float inv16 = 1.0f / 16.0f;
    mu.x *= inv16; mu.y *= inv16; mu.z *= inv16; mu.w *= inv16;
    float4 m2 = make_float4(0.f, 0.f, 0.f, 0.f);
#pragma unroll
    for (int g = 0; g < 16; g++) {
        float dx = t[g].x - mu.x, dy = t[g].y - mu.y;
        float dz = t[g].z - mu.z, dw = t[g].w - mu.w;
        m2.x = fmaf(dx, dx, m2.x); m2.y = fmaf(dy, dy, m2.y);
        m2.z = fmaf(dz, dz, m2.z); m2.w = fmaf(dw, dw, m2.w);
    }
    float4 rs;
    rs.x = rsqrtf(m2.x * inv16 + LN_EPS);
    rs.y = rsqrtf(m2.y * inv16 + LN_EPS);
    rs.z = rsqrtf(m2.z * inv16 + LN_EPS);
    rs.w = rsqrtf(m2.w * inv16 + LN_EPS);
#pragma unroll
    for (int g = 0; g < 16; g++) {
        float gg = gam[g], bb = bet[g];
        float4 o;
        o.x = fmaf((t[g].x - mu.x) * rs.x, gg, bb);
        o.y = fmaf((t[g].y - mu.y) * rs.y, gg, bb);
        o.z = fmaf((t[g].z - mu.z) * rs.z, gg, bb);
        o.w = fmaf((t[g].w - mu.w) * rs.w, gg, bb);
        *(float4*)&g_E[base0 + (size_t)g * PL] = o;
    }
}

__global__ void zero_rowsum_kernel()
{
    int i = blockIdx.x * 256 + threadIdx.x;
    if (i < NB * HN * NSEQ) g_rowsum[i] = 0.f;
}

// ---------------------------------------------------------------------------
extern "C" void kernel_launch(void* const* d_in, const int* in_sizes, int n_in,
                              void* d_out, int out_size)
{
    const float* x       = (const float*)d_in[0];
    const float* context = (const float*)d_in[1];
    const float* Wq      = (const float*)d_in[2];
    const float* Wkv     = (const float*)d_in[3];
    const float* Wtalk   = (const float*)d_in[4];
    const float* gamma   = (const float*)d_in[5];
    const float* beta    = (const float*)d_in[6];
    float* out = (float*)d_out;

    float *qp, *kvp;
    cudaGetSymbolAddress((void**)&qp, g_q);
    cudaGetSymbolAddress((void**)&kvp, g_kv);

    zero_rowsum_kernel<<<(NB * HN * NSEQ + 255) / 256, 256>>>();

    // q = x @ Wq^T (scaled), kv = context @ Wkv^T
    gemm_hmma_kernel<<<dim3(DMODEL / 128, (NB * NSEQ) / 128), 256>>>(
        x, Wq, qp, DMODEL, 0.125f);
    gemm_hmma_kernel<<<dim3(2048 / 128, (NB * NSEQ) / 128), 256>>>(
        context, Wkv, kvp, 2048, 1.0f);

    // v -> vt for the PV GEMM
    transpose_v_kernel<<<dim3(NSEQ / 32, DMODEL / 32, NB), dim3(32, 8)>>>();

    // exp(q k^T) per head + row sums
    scores_hmma_kernel<<<dim3(NSEQ / 128, NSEQ / 128, NB * HN), 256>>>();

    // softmax-normalize + talking heads + LN across heads (in place)
    talkln_kernel<<<dim3(4, NB * NSEQ), 128>>>(Wtalk, gamma, beta);

    // attn = aw @ v, written directly in final [b, n, h*d] layout
    pv_hmma_kernel<<<dim3(NSEQ / 128, NB * HN), 256>>>(out);
}